// round 5
// baseline (speedup 1.0000x reference)
#include <cuda_runtime.h>
#include <cuda_bf16.h>

#define NN 10000
#define IN_F 128
#define OUT_F 64
#define EDGES 320000
#define ALPHA 0.2f
#define GEMM_BM 64
#define GEMM_BLOCKS ((NN + GEMM_BM - 1) / GEMM_BM)   // 157
#define GEMM_SMEM ((IN_F * OUT_F + IN_F * GEMM_BM) * (int)sizeof(float))  // 64 KB

// ---------------- scratch (device globals; zero-initialized at load) --------
__device__ int   g_deg[NN];                  // invariant: zero at kernel_launch entry
__device__ int   g_rowstart[NN + 1];
__device__ int   g_cursor[NN];
__device__ int   g_cols[EDGES];
__device__ float g_Wh[NN * OUT_F];           // 2.56 MB (L2-resident)
__device__ float g_s1[NN];
__device__ float g_s2[NN];
__device__ float g_meanpart[GEMM_BLOCKS * OUT_F];
__device__ int   g_is32;                     // 0 = int64 (default), 1 = int32

// ---------------- helpers ---------------------------------------------------
__device__ __forceinline__ int edge_src(const void* p, int e, int is64) {
    return is64 ? (int)((const long long*)p)[e] : ((const int*)p)[e];
}
__device__ __forceinline__ int edge_dst(const void* p, int e, int is64) {
    return is64 ? (int)((const long long*)p)[EDGES + e] : ((const int*)p)[EDGES + e];
}
__device__ __forceinline__ float elu_f(float x) {
    return x > 0.f ? x : expm1f(x);
}

// ---------------- 1. detect edge_index dtype (1 tiny block) -----------------
// Reads only the first 256 int64s (2KB) — always in-bounds (E=320k).
// int64 data: all values are src ids in [0, NN) -> no thread flags.
// int32 data: each int64 read packs two node ids; looks "valid" only if the
// high word is 0 (P = 1e-4). P(all 256 look valid) = 1e-1024 -> certain.
// Benign-race plain store (all writers store 1); deterministic across replays.
__global__ void detect_kernel(const void* ei) {
    const long long* p = (const long long*)ei;
    long long v = p[threadIdx.x];
    bool bad = (v < 0 || v >= NN);
    unsigned m = __ballot_sync(0xFFFFFFFFu, bad);
    if (m != 0u && (threadIdx.x & 31) == 0) g_is32 = 1;
}

// ---------------- 2. Wh = h @ W  + fused s1/s2 + column-sum partials --------
// 4x4 register blocking: 256 threads = 16 row-groups x 16 col-groups.
// hsT reads are warp-broadcast (index depends only on tr) -> no padding needed.
// Dynamic smem (64 KB) because static limit is 48 KB.
__global__ void gemm_kernel(const float* __restrict__ h, const float* __restrict__ W,
                            const float* __restrict__ a) {
    extern __shared__ float smem[];
    float* Ws  = smem;                       // [128][64]  32 KB, [k][c]
    float* hsT = smem + IN_F * OUT_F;        // [128][64]  32 KB, [k][r]
    int t = threadIdx.x;
    int row0 = blockIdx.x * GEMM_BM;

    for (int i = t; i < IN_F * OUT_F; i += 256) Ws[i] = W[i];
    for (int i = t; i < GEMM_BM * IN_F; i += 256) {
        int r = i >> 7, k = i & 127;         // r in [0,64), k in [0,128)
        int gr = row0 + r;
        hsT[k * GEMM_BM + r] = (gr < NN) ? h[gr * IN_F + k] : 0.f;
    }
    __syncthreads();

    int tr = t >> 4, tc = t & 15;
    int rbase = tr * 4, cbase = tc * 4;
    float acc[4][4] = {};
#pragma unroll 4
    for (int k = 0; k < IN_F; k++) {
        float4 hv = *(const float4*)&hsT[k * GEMM_BM + rbase];
        float4 wv = *(const float4*)&Ws[k * OUT_F + cbase];
        acc[0][0] += hv.x * wv.x; acc[0][1] += hv.x * wv.y; acc[0][2] += hv.x * wv.z; acc[0][3] += hv.x * wv.w;
        acc[1][0] += hv.y * wv.x; acc[1][1] += hv.y * wv.y; acc[1][2] += hv.y * wv.z; acc[1][3] += hv.y * wv.w;
        acc[2][0] += hv.z * wv.x; acc[2][1] += hv.z * wv.y; acc[2][2] += hv.z * wv.z; acc[2][3] += hv.z * wv.w;
        acc[3][0] += hv.w * wv.x; acc[3][1] += hv.w * wv.y; acc[3][2] += hv.w * wv.z; acc[3][3] += hv.w * wv.w;
    }

    // store Wh (float4 per row)
#pragma unroll
    for (int j = 0; j < 4; j++) {
        int gr = row0 + rbase + j;
        if (gr < NN) {
            float4 v = make_float4(acc[j][0], acc[j][1], acc[j][2], acc[j][3]);
            *(float4*)&g_Wh[gr * OUT_F + cbase] = v;
        }
    }

    // ---- fused s1/s2: s1[r] = Wh[r,:]·a[0:64], s2[r] = Wh[r,:]·a[64:128] ----
    float av1[4], av2[4];
#pragma unroll
    for (int c = 0; c < 4; c++) { av1[c] = a[cbase + c]; av2[c] = a[64 + cbase + c]; }
#pragma unroll
    for (int j = 0; j < 4; j++) {
        float p1 = acc[j][0]*av1[0] + acc[j][1]*av1[1] + acc[j][2]*av1[2] + acc[j][3]*av1[3];
        float p2 = acc[j][0]*av2[0] + acc[j][1]*av2[1] + acc[j][2]*av2[2] + acc[j][3]*av2[3];
        // xor-reduce over the 16 col-group lanes (xor of bits 0..3 stays in row group)
#pragma unroll
        for (int off = 8; off > 0; off >>= 1) {
            p1 += __shfl_xor_sync(0xFFFFFFFFu, p1, off);
            p2 += __shfl_xor_sync(0xFFFFFFFFu, p2, off);
        }
        int gr = row0 + rbase + j;
        if (tc == 0 && gr < NN) { g_s1[gr] = p1; g_s2[gr] = p2; }
    }

    // ---- fused column-sum partials (zero-degree softmax fallback) ----------
    __syncthreads();                          // done with hsT: reuse as scratch
    float* cs = hsT;                          // 256*4 floats = 4 KB
    {
        float4 colsum = make_float4(acc[0][0] + acc[1][0] + acc[2][0] + acc[3][0],
                                    acc[0][1] + acc[1][1] + acc[2][1] + acc[3][1],
                                    acc[0][2] + acc[1][2] + acc[2][2] + acc[3][2],
                                    acc[0][3] + acc[1][3] + acc[2][3] + acc[3][3]);
        *(float4*)&cs[t * 4] = colsum;
    }
    __syncthreads();
    if (t < 64) {
        int tcq = t >> 2, ccq = t & 3;
        float s = 0.f;
#pragma unroll
        for (int tr2 = 0; tr2 < 16; tr2++) s += cs[(tr2 * 16 + tcq) * 4 + ccq];
        g_meanpart[blockIdx.x * OUT_F + t] = s;
    }
}

// ---------------- 3. degree count (dups included) ---------------------------
__global__ void count_kernel(const void* ei) {
    int is64 = !g_is32;
    int e = blockIdx.x * blockDim.x + threadIdx.x;      // grid == EDGES exactly
    int s = edge_src(ei, e, is64);
    atomicAdd(&g_deg[s], 1);
}

// ---------------- 4. exclusive prefix scan (1 block) + restore g_deg=0 ------
#define SCAN_PT 10   // 1024 threads * 10 = 10240 >= NN
__global__ void scan_kernel() {
    __shared__ int wsum[32];
    int t = threadIdx.x;
    int lane = t & 31, wid = t >> 5;
    int base = t * SCAN_PT;
    int v[SCAN_PT];
    int s = 0;
#pragma unroll
    for (int i = 0; i < SCAN_PT; i++) {
        int idx = base + i;
        int x = 0;
        if (idx < NN) { x = g_deg[idx]; g_deg[idx] = 0; }  // restore invariant
        v[i] = s;
        s += x;
    }
    int inc = s;
#pragma unroll
    for (int off = 1; off < 32; off <<= 1) {
        int y = __shfl_up_sync(0xFFFFFFFFu, inc, off);
        if (lane >= off) inc += y;
    }
    if (lane == 31) wsum[wid] = inc;
    __syncthreads();
    if (wid == 0) {
        int x = wsum[lane];
        int ix = x;
#pragma unroll
        for (int off = 1; off < 32; off <<= 1) {
            int y = __shfl_up_sync(0xFFFFFFFFu, ix, off);
            if (lane >= off) ix += y;
        }
        wsum[lane] = ix - x;
    }
    __syncthreads();
    int tbase = wsum[wid] + (inc - s);
#pragma unroll
    for (int i = 0; i < SCAN_PT; i++) {
        int idx = base + i;
        if (idx < NN) {
            g_rowstart[idx] = tbase + v[i];
            g_cursor[idx]   = tbase + v[i];
        }
    }
    if (t == 1023) g_rowstart[NN] = tbase + s;
}

// ---------------- 5. scatter dst ids into CSR (dups included) ---------------
__global__ void scatter_kernel(const void* ei) {
    int is64 = !g_is32;
    int e = blockIdx.x * blockDim.x + threadIdx.x;      // grid == EDGES exactly
    int s = edge_src(ei, e, is64);
    int d = edge_dst(ei, e, is64);
    int pos = atomicAdd(&g_cursor[s], 1);
    g_cols[pos] = d;
}

// ---------------- 6. warp-per-row: dedup, softmax, aggregate, ELU -----------
__global__ void row_kernel(float* __restrict__ out) {
    int gtid = blockIdx.x * blockDim.x + threadIdx.x;
    int row = gtid >> 5;
    int lane = gtid & 31;
    if (row >= NN) return;
    int beg = g_rowstart[row];
    int end = g_rowstart[row + 1];
    float a0 = 0.f, a1 = 0.f, swl = 0.f;
    float s1r = g_s1[row];

    for (int p0 = beg; p0 < end; p0 += 32) {
        int p = p0 + lane;
        int c = -1;
        float w = 0.f;
        if (p < end) {
            c = g_cols[p];
            // keep only the FIRST occurrence of each dst within this row
            bool keep = true;
            for (int q = beg; q < p; q++)
                if (g_cols[q] == c) { keep = false; break; }
            if (keep) {
                float x = s1r + g_s2[c];
                float lr = x > 0.f ? x : ALPHA * x;   // leaky relu
                w = expf(lr);
                swl += w;
            } else {
                c = -1;
            }
        }
        int cnt = end - p0; if (cnt > 32) cnt = 32;
        for (int j = 0; j < cnt; j++) {
            int cc = __shfl_sync(0xFFFFFFFFu, c, j);
            float ww = __shfl_sync(0xFFFFFFFFu, w, j);
            if (cc >= 0) {
                a0 += ww * g_Wh[cc * OUT_F + lane];
                a1 += ww * g_Wh[cc * OUT_F + 32 + lane];
            }
        }
    }
    float sw = swl;
#pragma unroll
    for (int off = 16; off > 0; off >>= 1)
        sw += __shfl_xor_sync(0xFFFFFFFFu, sw, off);

    if (beg == end) {
        // softmax over an all -inf row is uniform -> h' = column mean of Wh
        float m0 = 0.f, m1 = 0.f;
        for (int b = 0; b < GEMM_BLOCKS; b++) {
            m0 += g_meanpart[b * OUT_F + lane];
            m1 += g_meanpart[b * OUT_F + 32 + lane];
        }
        a0 = m0 / (float)NN;
        a1 = m1 / (float)NN;
        sw = 1.f;
    }
    float inv = 1.f / sw;
    out[row * OUT_F + lane]      = elu_f(a0 * inv);
    out[row * OUT_F + 32 + lane] = elu_f(a1 * inv);
}

// ---------------- launch ----------------------------------------------------
extern "C" void kernel_launch(void* const* d_in, const int* in_sizes, int n_in,
                              void* d_out, int out_size) {
    const float* h  = (const float*)d_in[0];
    const void*  ei = d_in[1];
    const float* W  = (const float*)d_in[2];
    const float* a  = (const float*)d_in[3];
    float* out = (float*)d_out;

    // opt into >48KB dynamic smem for the GEMM (idempotent, graph-capture-safe)
    cudaFuncSetAttribute(gemm_kernel, cudaFuncAttributeMaxDynamicSharedMemorySize,
                         GEMM_SMEM);

    detect_kernel<<<1, 256>>>(ei);
    gemm_kernel<<<GEMM_BLOCKS, 256, GEMM_SMEM>>>(h, W, a);
    count_kernel<<<EDGES / 256, 256>>>(ei);
    scan_kernel<<<1, 1024>>>();
    scatter_kernel<<<EDGES / 256, 256>>>(ei);
    row_kernel<<<(NN * 32 + 255) / 256, 256>>>(out);
}

// round 6
// speedup vs baseline: 1.1355x; 1.1355x over previous
#include <cuda_runtime.h>
#include <cuda_bf16.h>

#define NN 10000
#define IN_F 128
#define OUT_F 64
#define EDGES 320000
#define ALPHA 0.2f
#define GEMM_BM 64
#define GEMM_BLOCKS ((NN + GEMM_BM - 1) / GEMM_BM)   // 157
#define GEMM_SMEM ((IN_F * OUT_F + IN_F * GEMM_BM) * (int)sizeof(float))  // 64 KB
#define CAP 128        // bucket capacity; max degree of Poisson(32) over 10k rows ~ 56

// ---------------- scratch (device globals; zero-initialized at load) --------
__device__ int   g_deg[NN];                  // invariant: zero at kernel_launch entry
__device__ int   g_cols[NN * CAP];           // 5.12 MB padded buckets
__device__ float g_Wh[NN * OUT_F];           // 2.56 MB (L2-resident)
__device__ float g_s1[NN];
__device__ float g_s2[NN];
__device__ float g_meanpart[GEMM_BLOCKS * OUT_F];

// ---------------- helpers ---------------------------------------------------
__device__ __forceinline__ int edge_src(const void* p, int e, int is64) {
    return is64 ? (int)((const long long*)p)[e] : ((const int*)p)[e];
}
__device__ __forceinline__ int edge_dst(const void* p, int e, int is64) {
    return is64 ? (int)((const long long*)p)[EDGES + e] : ((const int*)p)[EDGES + e];
}
__device__ __forceinline__ float elu_f(float x) {
    return x > 0.f ? x : expm1f(x);
}

// ---------------- 1. Wh = h @ W  + fused s1/s2 + column-sum partials --------
// 4x4 register blocking: 256 threads = 16 row-groups x 16 col-groups.
// hsT reads are warp-broadcast (index depends only on tr) -> no padding needed.
// Dynamic smem (64 KB) because static limit is 48 KB.
__global__ void gemm_kernel(const float* __restrict__ h, const float* __restrict__ W,
                            const float* __restrict__ a) {
    extern __shared__ float smem[];
    float* Ws  = smem;                       // [128][64]  32 KB, [k][c]
    float* hsT = smem + IN_F * OUT_F;        // [128][64]  32 KB, [k][r]
    int t = threadIdx.x;
    int row0 = blockIdx.x * GEMM_BM;

    for (int i = t; i < IN_F * OUT_F; i += 256) Ws[i] = W[i];
    for (int i = t; i < GEMM_BM * IN_F; i += 256) {
        int r = i >> 7, k = i & 127;         // r in [0,64), k in [0,128)
        int gr = row0 + r;
        hsT[k * GEMM_BM + r] = (gr < NN) ? h[gr * IN_F + k] : 0.f;
    }
    __syncthreads();

    int tr = t >> 4, tc = t & 15;
    int rbase = tr * 4, cbase = tc * 4;
    float acc[4][4] = {};
#pragma unroll 4
    for (int k = 0; k < IN_F; k++) {
        float4 hv = *(const float4*)&hsT[k * GEMM_BM + rbase];
        float4 wv = *(const float4*)&Ws[k * OUT_F + cbase];
        acc[0][0] += hv.x * wv.x; acc[0][1] += hv.x * wv.y; acc[0][2] += hv.x * wv.z; acc[0][3] += hv.x * wv.w;
        acc[1][0] += hv.y * wv.x; acc[1][1] += hv.y * wv.y; acc[1][2] += hv.y * wv.z; acc[1][3] += hv.y * wv.w;
        acc[2][0] += hv.z * wv.x; acc[2][1] += hv.z * wv.y; acc[2][2] += hv.z * wv.z; acc[2][3] += hv.z * wv.w;
        acc[3][0] += hv.w * wv.x; acc[3][1] += hv.w * wv.y; acc[3][2] += hv.w * wv.z; acc[3][3] += hv.w * wv.w;
    }

    // store Wh (float4 per row)
#pragma unroll
    for (int j = 0; j < 4; j++) {
        int gr = row0 + rbase + j;
        if (gr < NN) {
            float4 v = make_float4(acc[j][0], acc[j][1], acc[j][2], acc[j][3]);
            *(float4*)&g_Wh[gr * OUT_F + cbase] = v;
        }
    }

    // ---- fused s1/s2: s1[r] = Wh[r,:]·a[0:64], s2[r] = Wh[r,:]·a[64:128] ----
    float av1[4], av2[4];
#pragma unroll
    for (int c = 0; c < 4; c++) { av1[c] = a[cbase + c]; av2[c] = a[64 + cbase + c]; }
#pragma unroll
    for (int j = 0; j < 4; j++) {
        float p1 = acc[j][0]*av1[0] + acc[j][1]*av1[1] + acc[j][2]*av1[2] + acc[j][3]*av1[3];
        float p2 = acc[j][0]*av2[0] + acc[j][1]*av2[1] + acc[j][2]*av2[2] + acc[j][3]*av2[3];
        // xor-reduce over the 16 col-group lanes (xor of bits 0..3 stays in row group)
#pragma unroll
        for (int off = 8; off > 0; off >>= 1) {
            p1 += __shfl_xor_sync(0xFFFFFFFFu, p1, off);
            p2 += __shfl_xor_sync(0xFFFFFFFFu, p2, off);
        }
        int gr = row0 + rbase + j;
        if (tc == 0 && gr < NN) { g_s1[gr] = p1; g_s2[gr] = p2; }
    }

    // ---- fused column-sum partials (zero-degree softmax fallback) ----------
    __syncthreads();                          // done with hsT: reuse as scratch
    float* cs = hsT;                          // 256*4 floats = 4 KB
    {
        float4 colsum = make_float4(acc[0][0] + acc[1][0] + acc[2][0] + acc[3][0],
                                    acc[0][1] + acc[1][1] + acc[2][1] + acc[3][1],
                                    acc[0][2] + acc[1][2] + acc[2][2] + acc[3][2],
                                    acc[0][3] + acc[1][3] + acc[2][3] + acc[3][3]);
        *(float4*)&cs[t * 4] = colsum;
    }
    __syncthreads();
    if (t < 64) {
        int tcq = t >> 2, ccq = t & 3;
        float s = 0.f;
#pragma unroll
        for (int tr2 = 0; tr2 < 16; tr2++) s += cs[(tr2 * 16 + tcq) * 4 + ccq];
        g_meanpart[blockIdx.x * OUT_F + t] = s;
    }
}

// ---------------- 2. bucket scatter (single pass, inline dtype detect) ------
// dtype detect per block: warp 0 reads the FIRST 32 int64s (L2-broadcast after
// block 0). int64 data: all are src ids in [0, NN). int32 data: the read packs
// two node ids -> looks valid only if high word == 0 (P = 1e-4 each);
// P(all 32 look valid) = 1e-128 -> detection certain. No global flag needed.
__global__ void scatter_kernel(const void* ei) {
    __shared__ int s_is64;
    int t = threadIdx.x;
    if (t < 32) {
        const long long* p = (const long long*)ei;
        long long v = p[t];
        bool bad = (v < 0 || v >= NN);
        unsigned m = __ballot_sync(0xFFFFFFFFu, bad);
        if (t == 0) s_is64 = (m == 0u) ? 1 : 0;
    }
    __syncthreads();
    int is64 = s_is64;

    int e = blockIdx.x * blockDim.x + t;      // grid == EDGES exactly
    int s = edge_src(ei, e, is64);
    int d = edge_dst(ei, e, is64);
    int pos = atomicAdd(&g_deg[s], 1);
    if (pos < CAP) g_cols[s * CAP + pos] = d; // clamp: overflow impossible in practice
}

// ---------------- 3. warp-per-row: dedup, softmax, aggregate, ELU -----------
__global__ void row_kernel(float* __restrict__ out) {
    int gtid = blockIdx.x * blockDim.x + threadIdx.x;
    int row = gtid >> 5;
    int lane = gtid & 31;
    if (row >= NN) return;

    int deg = g_deg[row];
    if (deg > CAP) deg = CAP;
    __syncwarp();
    if (lane == 0) g_deg[row] = 0;            // restore zero-invariant for replay

    const int* bucket = &g_cols[row * CAP];
    float a0 = 0.f, a1 = 0.f, swl = 0.f;
    float s1r = g_s1[row];

    for (int p0 = 0; p0 < deg; p0 += 32) {
        int p = p0 + lane;
        int c = -1;
        float w = 0.f;
        if (p < deg) {
            c = bucket[p];
            // keep only the FIRST occurrence of each dst within this row
            bool keep = true;
            for (int q = 0; q < p; q++)
                if (bucket[q] == c) { keep = false; break; }
            if (keep) {
                float x = s1r + g_s2[c];
                float lr = x > 0.f ? x : ALPHA * x;   // leaky relu
                w = expf(lr);
                swl += w;
            } else {
                c = -1;
            }
        }
        int cnt = deg - p0; if (cnt > 32) cnt = 32;
        for (int j = 0; j < cnt; j++) {
            int cc = __shfl_sync(0xFFFFFFFFu, c, j);
            float ww = __shfl_sync(0xFFFFFFFFu, w, j);
            if (cc >= 0) {
                a0 += ww * g_Wh[cc * OUT_F + lane];
                a1 += ww * g_Wh[cc * OUT_F + 32 + lane];
            }
        }
    }
    float sw = swl;
#pragma unroll
    for (int off = 16; off > 0; off >>= 1)
        sw += __shfl_xor_sync(0xFFFFFFFFu, sw, off);

    if (deg == 0) {
        // softmax over an all -inf row is uniform -> h' = column mean of Wh
        float m0 = 0.f, m1 = 0.f;
        for (int b = 0; b < GEMM_BLOCKS; b++) {
            m0 += g_meanpart[b * OUT_F + lane];
            m1 += g_meanpart[b * OUT_F + 32 + lane];
        }
        a0 = m0 / (float)NN;
        a1 = m1 / (float)NN;
        sw = 1.f;
    }
    float inv = 1.f / sw;
    out[row * OUT_F + lane]      = elu_f(a0 * inv);
    out[row * OUT_F + 32 + lane] = elu_f(a1 * inv);
}

// ---------------- launch ----------------------------------------------------
extern "C" void kernel_launch(void* const* d_in, const int* in_sizes, int n_in,
                              void* d_out, int out_size) {
    const float* h  = (const float*)d_in[0];
    const void*  ei = d_in[1];
    const float* W  = (const float*)d_in[2];
    const float* a  = (const float*)d_in[3];
    float* out = (float*)d_out;

    // opt into >48KB dynamic smem for the GEMM (idempotent, graph-capture-safe)
    cudaFuncSetAttribute(gemm_kernel, cudaFuncAttributeMaxDynamicSharedMemorySize,
                         GEMM_SMEM);

    gemm_kernel<<<GEMM_BLOCKS, 256, GEMM_SMEM>>>(h, W, a);
    scatter_kernel<<<EDGES / 256, 256>>>(ei);
    row_kernel<<<(NN * 32 + 255) / 256, 256>>>(out);
}

// round 7
// speedup vs baseline: 1.1998x; 1.0566x over previous
#include <cuda_runtime.h>
#include <cuda_bf16.h>

#define NN 10000
#define IN_F 128
#define OUT_F 64
#define EDGES 320000
#define ALPHA 0.2f
#define GEMM_BM 64
#define GEMM_BLOCKS ((NN + GEMM_BM - 1) / GEMM_BM)   // 157
#define SCAT_BLOCKS 287                               // 157+287 = 444 = 148*3 (one wave)
#define HS_LD 132                                     // row stride (pad, 16B-aligned)
#define FUSED_SMEM ((IN_F * OUT_F + GEMM_BM * HS_LD) * (int)sizeof(float))  // 66560 B
#define CAP 128        // bucket capacity; max degree of Poisson(32) over 10k rows ~ 56

// ---------------- scratch (device globals; zero-initialized at load) --------
__device__ int   g_deg[NN];                  // invariant: zero at kernel_launch entry
__device__ int   g_cols[NN * CAP];           // 5.12 MB padded buckets
__device__ float g_Wh[NN * OUT_F];           // 2.56 MB (L2-resident)
__device__ float g_s1[NN];
__device__ float g_s2[NN];
__device__ float g_meanpart[GEMM_BLOCKS * OUT_F];

// ---------------- helpers ---------------------------------------------------
__device__ __forceinline__ int edge_src(const void* p, int e, int is64) {
    return is64 ? (int)((const long long*)p)[e] : ((const int*)p)[e];
}
__device__ __forceinline__ int edge_dst(const void* p, int e, int is64) {
    return is64 ? (int)((const long long*)p)[EDGES + e] : ((const int*)p)[EDGES + e];
}
__device__ __forceinline__ float elu_f(float x) {
    return x > 0.f ? x : expm1f(x);
}

// ---------------- 1. fused: GEMM(+s1/s2+mean) blocks || scatter blocks ------
// blockIdx < GEMM_BLOCKS : one 64-row tile of Wh = h @ W, fused epilogues.
// blockIdx >= GEMM_BLOCKS: grid-stride bucket scatter of the edge list.
// Both are independent; one launch, one wave (444 blocks, 3/SM @ 65KB smem).
__global__ void fused_kernel(const float* __restrict__ h, const float* __restrict__ W,
                             const float* __restrict__ a, const void* __restrict__ ei) {
    int t = threadIdx.x;

    if (blockIdx.x >= GEMM_BLOCKS) {
        // ------------------- scatter role --------------------------------
        // dtype detect: warp 0 reads the FIRST 32 int64s (L2 broadcast).
        // int64 data: all are src ids in [0, NN). int32 data: each read packs
        // two node ids -> looks valid only if high word == 0 (P = 1e-4 each);
        // P(all 32 look valid) = 1e-128 -> detection certain.
        __shared__ int s_is64;
        if (t < 32) {
            const long long* p = (const long long*)ei;
            long long v = p[t];
            bool bad = (v < 0 || v >= NN);
            unsigned m = __ballot_sync(0xFFFFFFFFu, bad);
            if (t == 0) s_is64 = (m == 0u) ? 1 : 0;
        }
        __syncthreads();
        int is64 = s_is64;
        int sbid = blockIdx.x - GEMM_BLOCKS;
        for (int e = sbid * 256 + t; e < EDGES; e += SCAT_BLOCKS * 256) {
            int s = edge_src(ei, e, is64);
            int d = edge_dst(ei, e, is64);
            int pos = atomicAdd(&g_deg[s], 1);
            if (pos < CAP) g_cols[s * CAP + pos] = d;  // clamp (never hit in practice)
        }
        return;
    }

    // ---------------------- gemm role ------------------------------------
    extern __shared__ float smem[];
    float* Ws = smem;                        // [128][64]  32 KB, [k][c]
    float* hs = smem + IN_F * OUT_F;         // [64][132]  33.8 KB, [r][k] row-major
    int row0 = blockIdx.x * GEMM_BM;

    for (int i = t; i < IN_F * OUT_F; i += 256) Ws[i] = W[i];
    // coalesced float4 global loads, conflict-free float4 smem stores
    for (int i = t; i < GEMM_BM * (IN_F / 4); i += 256) {
        int r = i >> 5, cq = i & 31;         // r in [0,64), cq in [0,32)
        int gr = row0 + r;
        float4 v = make_float4(0.f, 0.f, 0.f, 0.f);
        if (gr < NN) v = *(const float4*)&h[gr * IN_F + cq * 4];
        *(float4*)&hs[r * HS_LD + cq * 4] = v;
    }
    __syncthreads();

    int tr = t >> 4, tc = t & 15;
    int rbase = tr * 4, cbase = tc * 4;
    const float* h0 = &hs[(rbase + 0) * HS_LD];
    const float* h1 = &hs[(rbase + 1) * HS_LD];
    const float* h2 = &hs[(rbase + 2) * HS_LD];
    const float* h3 = &hs[(rbase + 3) * HS_LD];
    float acc[4][4] = {};
#pragma unroll 4
    for (int k = 0; k < IN_F; k++) {
        float4 wv = *(const float4*)&Ws[k * OUT_F + cbase];
        float a0v = h0[k], a1v = h1[k], a2v = h2[k], a3v = h3[k];  // broadcast LDS
        acc[0][0] += a0v * wv.x; acc[0][1] += a0v * wv.y; acc[0][2] += a0v * wv.z; acc[0][3] += a0v * wv.w;
        acc[1][0] += a1v * wv.x; acc[1][1] += a1v * wv.y; acc[1][2] += a1v * wv.z; acc[1][3] += a1v * wv.w;
        acc[2][0] += a2v * wv.x; acc[2][1] += a2v * wv.y; acc[2][2] += a2v * wv.z; acc[2][3] += a2v * wv.w;
        acc[3][0] += a3v * wv.x; acc[3][1] += a3v * wv.y; acc[3][2] += a3v * wv.z; acc[3][3] += a3v * wv.w;
    }

    // store Wh (float4 per row)
#pragma unroll
    for (int j = 0; j < 4; j++) {
        int gr = row0 + rbase + j;
        if (gr < NN) {
            float4 v = make_float4(acc[j][0], acc[j][1], acc[j][2], acc[j][3]);
            *(float4*)&g_Wh[gr * OUT_F + cbase] = v;
        }
    }

    // ---- fused s1/s2: s1[r] = Wh[r,:]·a[0:64], s2[r] = Wh[r,:]·a[64:128] ----
    float av1[4], av2[4];
#pragma unroll
    for (int c = 0; c < 4; c++) { av1[c] = a[cbase + c]; av2[c] = a[64 + cbase + c]; }
#pragma unroll
    for (int j = 0; j < 4; j++) {
        float p1 = acc[j][0]*av1[0] + acc[j][1]*av1[1] + acc[j][2]*av1[2] + acc[j][3]*av1[3];
        float p2 = acc[j][0]*av2[0] + acc[j][1]*av2[1] + acc[j][2]*av2[2] + acc[j][3]*av2[3];
        // xor-reduce over the 16 col-group lanes (xor of bits 0..3 stays in row group)
#pragma unroll
        for (int off = 8; off > 0; off >>= 1) {
            p1 += __shfl_xor_sync(0xFFFFFFFFu, p1, off);
            p2 += __shfl_xor_sync(0xFFFFFFFFu, p2, off);
        }
        int gr = row0 + rbase + j;
        if (tc == 0 && gr < NN) { g_s1[gr] = p1; g_s2[gr] = p2; }
    }

    // ---- fused column-sum partials (zero-degree softmax fallback) ----------
    __syncthreads();                          // done with hs: reuse as scratch
    float* cs = hs;                           // 256*4 floats = 4 KB
    {
        float4 colsum = make_float4(acc[0][0] + acc[1][0] + acc[2][0] + acc[3][0],
                                    acc[0][1] + acc[1][1] + acc[2][1] + acc[3][1],
                                    acc[0][2] + acc[1][2] + acc[2][2] + acc[3][2],
                                    acc[0][3] + acc[1][3] + acc[2][3] + acc[3][3]);
        *(float4*)&cs[t * 4] = colsum;
    }
    __syncthreads();
    if (t < 64) {
        int tcq = t >> 2, ccq = t & 3;
        float s = 0.f;
#pragma unroll
        for (int tr2 = 0; tr2 < 16; tr2++) s += cs[(tr2 * 16 + tcq) * 4 + ccq];
        g_meanpart[blockIdx.x * OUT_F + t] = s;
    }
}

// ---------------- 2. warp-per-row: shuffle-dedup, softmax, aggregate, ELU ---
__global__ void row_kernel(float* __restrict__ out) {
    int gtid = blockIdx.x * blockDim.x + threadIdx.x;
    int row = gtid >> 5;
    int lane = gtid & 31;
    if (row >= NN) return;

    int deg = g_deg[row];
    if (deg > CAP) deg = CAP;
    __syncwarp();
    if (lane == 0) g_deg[row] = 0;            // restore zero-invariant for replay

    const int* bucket = &g_cols[row * CAP];
    float a0 = 0.f, a1 = 0.f, swl = 0.f;
    float s1r = g_s1[row];

    int prevc[CAP / 32];                      // previous chunks' dst ids (registers)
    int nchunks = (deg + 31) >> 5;
    for (int ch = 0; ch < nchunks; ch++) {
        int p0 = ch << 5;
        int p = p0 + lane;
        int c = (p < deg) ? bucket[p] : -1;   // -1 never matches a real id

        // dedup vs previous chunks (register-resident, shuffle broadcast)
        bool dup = false;
#pragma unroll 3
        for (int q = 0; q < ch; q++) {
            int pv = prevc[q];
#pragma unroll
            for (int j = 0; j < 32; j++) {
                int cc = __shfl_sync(0xFFFFFFFFu, pv, j);
                if (cc == c && c >= 0) dup = true;
            }
        }
        // dedup within this chunk (keep lowest lane)
        {
            int myc = c;
#pragma unroll
            for (int j = 0; j < 32; j++) {
                int cc = __shfl_sync(0xFFFFFFFFu, myc, j);
                if (j < lane && cc == c && c >= 0) dup = true;
            }
        }

        float w = 0.f;
        int ceff = -1;
        if (c >= 0 && !dup) {
            float x = s1r + g_s2[c];
            float lr = x > 0.f ? x : ALPHA * x;   // leaky relu
            w = expf(lr);
            swl += w;
            ceff = c;
        }

        int cnt = deg - p0; if (cnt > 32) cnt = 32;
        for (int j = 0; j < cnt; j++) {
            int cc = __shfl_sync(0xFFFFFFFFu, ceff, j);
            float ww = __shfl_sync(0xFFFFFFFFu, w, j);
            if (cc >= 0) {
                a0 += ww * g_Wh[cc * OUT_F + lane];
                a1 += ww * g_Wh[cc * OUT_F + 32 + lane];
            }
        }
        if (ch < CAP / 32) prevc[ch] = c;
    }

    float sw = swl;
#pragma unroll
    for (int off = 16; off > 0; off >>= 1)
        sw += __shfl_xor_sync(0xFFFFFFFFu, sw, off);

    if (deg == 0) {
        // softmax over an all -inf row is uniform -> h' = column mean of Wh
        float m0 = 0.f, m1 = 0.f;
        for (int b = 0; b < GEMM_BLOCKS; b++) {
            m0 += g_meanpart[b * OUT_F + lane];
            m1 += g_meanpart[b * OUT_F + 32 + lane];
        }
        a0 = m0 / (float)NN;
        a1 = m1 / (float)NN;
        sw = 1.f;
    }
    float inv = 1.f / sw;
    out[row * OUT_F + lane]      = elu_f(a0 * inv);
    out[row * OUT_F + 32 + lane] = elu_f(a1 * inv);
}

// ---------------- launch ----------------------------------------------------
extern "C" void kernel_launch(void* const* d_in, const int* in_sizes, int n_in,
                              void* d_out, int out_size) {
    const float* h  = (const float*)d_in[0];
    const void*  ei = d_in[1];
    const float* W  = (const float*)d_in[2];
    const float* a  = (const float*)d_in[3];
    float* out = (float*)d_out;

    // opt into >48KB dynamic smem (idempotent, graph-capture-safe)
    cudaFuncSetAttribute(fused_kernel, cudaFuncAttributeMaxDynamicSharedMemorySize,
                         FUSED_SMEM);

    fused_kernel<<<GEMM_BLOCKS + SCAT_BLOCKS, 256, FUSED_SMEM>>>(h, W, a, ei);
    row_kernel<<<(NN * 32 + 255) / 256, 256>>>(out);
}

// round 8
// speedup vs baseline: 1.6698x; 1.3917x over previous
#include <cuda_runtime.h>
#include <cuda_bf16.h>

#define NN 10000
#define IN_F 128
#define OUT_F 64
#define EDGES 320000
#define ALPHA 0.2f
#define GEMM_BM 64
#define GEMM_BLOCKS ((NN + GEMM_BM - 1) / GEMM_BM)   // 157
#define SCAT_BLOCKS 287                               // 157+287 = 444 = 148*3 (one wave)
#define HS_LD 132                                     // row stride (pad, 16B-aligned)
#define FUSED_SMEM ((IN_F * OUT_F + GEMM_BM * HS_LD) * (int)sizeof(float))  // 66560 B
#define CAP 128        // bucket capacity; max degree of Poisson(32) over 10k rows ~ 56

// ---------------- scratch (device globals; zero-initialized at load) --------
__device__ int   g_deg[NN];                  // invariant: zero at kernel_launch entry
__device__ int   g_cols[NN * CAP];           // 5.12 MB padded buckets
__device__ float g_Wh[NN * OUT_F];           // 2.56 MB (L2-resident)
__device__ float g_s1[NN];
__device__ float g_s2[NN];
__device__ float g_meanpart[GEMM_BLOCKS * OUT_F];

// ---------------- helpers ---------------------------------------------------
__device__ __forceinline__ int edge_src(const void* p, int e, int is64) {
    return is64 ? (int)((const long long*)p)[e] : ((const int*)p)[e];
}
__device__ __forceinline__ int edge_dst(const void* p, int e, int is64) {
    return is64 ? (int)((const long long*)p)[EDGES + e] : ((const int*)p)[EDGES + e];
}
__device__ __forceinline__ float elu_f(float x) {
    return x > 0.f ? x : expm1f(x);
}

// ---------------- 1. fused: GEMM(+s1/s2+mean) blocks || scatter blocks ------
// blockIdx < GEMM_BLOCKS : one 64-row tile of Wh = h @ W, fused epilogues.
// blockIdx >= GEMM_BLOCKS: grid-stride bucket scatter of the edge list.
// Both are independent; one launch, one wave (444 blocks, 3/SM @ 65KB smem).
__global__ void fused_kernel(const float* __restrict__ h, const float* __restrict__ W,
                             const float* __restrict__ a, const void* __restrict__ ei) {
    int t = threadIdx.x;

    if (blockIdx.x >= GEMM_BLOCKS) {
        // ------------------- scatter role --------------------------------
        // dtype detect: warp 0 reads the FIRST 32 int64s (L2 broadcast).
        // int64 data: all are src ids in [0, NN). int32 data: each read packs
        // two node ids -> looks valid only if high word == 0 (P = 1e-4 each);
        // P(all 32 look valid) = 1e-128 -> detection certain.
        __shared__ int s_is64;
        if (t < 32) {
            const long long* p = (const long long*)ei;
            long long v = p[t];
            bool bad = (v < 0 || v >= NN);
            unsigned m = __ballot_sync(0xFFFFFFFFu, bad);
            if (t == 0) s_is64 = (m == 0u) ? 1 : 0;
        }
        __syncthreads();
        int is64 = s_is64;
        int sbid = blockIdx.x - GEMM_BLOCKS;
        for (int e = sbid * 256 + t; e < EDGES; e += SCAT_BLOCKS * 256) {
            int s = edge_src(ei, e, is64);
            int d = edge_dst(ei, e, is64);
            int pos = atomicAdd(&g_deg[s], 1);
            if (pos < CAP) g_cols[s * CAP + pos] = d;  // clamp (never hit in practice)
        }
        return;
    }

    // ---------------------- gemm role ------------------------------------
    extern __shared__ float smem[];
    float* Ws = smem;                        // [128][64]  32 KB, [k][c]
    float* hs = smem + IN_F * OUT_F;         // [64][132]  33.8 KB, [r][k] row-major
    int row0 = blockIdx.x * GEMM_BM;

    for (int i = t; i < IN_F * OUT_F; i += 256) Ws[i] = W[i];
    // coalesced float4 global loads, conflict-free float4 smem stores
    for (int i = t; i < GEMM_BM * (IN_F / 4); i += 256) {
        int r = i >> 5, cq = i & 31;         // r in [0,64), cq in [0,32)
        int gr = row0 + r;
        float4 v = make_float4(0.f, 0.f, 0.f, 0.f);
        if (gr < NN) v = *(const float4*)&h[gr * IN_F + cq * 4];
        *(float4*)&hs[r * HS_LD + cq * 4] = v;
    }
    __syncthreads();

    int tr = t >> 4, tc = t & 15;
    int rbase = tr * 4, cbase = tc * 4;
    const float* h0 = &hs[(rbase + 0) * HS_LD];
    const float* h1 = &hs[(rbase + 1) * HS_LD];
    const float* h2 = &hs[(rbase + 2) * HS_LD];
    const float* h3 = &hs[(rbase + 3) * HS_LD];
    float acc[4][4] = {};
#pragma unroll 4
    for (int k = 0; k < IN_F; k++) {
        float4 wv = *(const float4*)&Ws[k * OUT_F + cbase];
        float a0v = h0[k], a1v = h1[k], a2v = h2[k], a3v = h3[k];  // broadcast LDS
        acc[0][0] += a0v * wv.x; acc[0][1] += a0v * wv.y; acc[0][2] += a0v * wv.z; acc[0][3] += a0v * wv.w;
        acc[1][0] += a1v * wv.x; acc[1][1] += a1v * wv.y; acc[1][2] += a1v * wv.z; acc[1][3] += a1v * wv.w;
        acc[2][0] += a2v * wv.x; acc[2][1] += a2v * wv.y; acc[2][2] += a2v * wv.z; acc[2][3] += a2v * wv.w;
        acc[3][0] += a3v * wv.x; acc[3][1] += a3v * wv.y; acc[3][2] += a3v * wv.z; acc[3][3] += a3v * wv.w;
    }

    // store Wh (float4 per row)
#pragma unroll
    for (int j = 0; j < 4; j++) {
        int gr = row0 + rbase + j;
        if (gr < NN) {
            float4 v = make_float4(acc[j][0], acc[j][1], acc[j][2], acc[j][3]);
            *(float4*)&g_Wh[gr * OUT_F + cbase] = v;
        }
    }

    // ---- fused s1/s2: s1[r] = Wh[r,:]·a[0:64], s2[r] = Wh[r,:]·a[64:128] ----
    float av1[4], av2[4];
#pragma unroll
    for (int c = 0; c < 4; c++) { av1[c] = a[cbase + c]; av2[c] = a[64 + cbase + c]; }
#pragma unroll
    for (int j = 0; j < 4; j++) {
        float p1 = acc[j][0]*av1[0] + acc[j][1]*av1[1] + acc[j][2]*av1[2] + acc[j][3]*av1[3];
        float p2 = acc[j][0]*av2[0] + acc[j][1]*av2[1] + acc[j][2]*av2[2] + acc[j][3]*av2[3];
        // xor-reduce over the 16 col-group lanes (xor of bits 0..3 stays in row group)
#pragma unroll
        for (int off = 8; off > 0; off >>= 1) {
            p1 += __shfl_xor_sync(0xFFFFFFFFu, p1, off);
            p2 += __shfl_xor_sync(0xFFFFFFFFu, p2, off);
        }
        int gr = row0 + rbase + j;
        if (tc == 0 && gr < NN) { g_s1[gr] = p1; g_s2[gr] = p2; }
    }

    // ---- fused column-sum partials (zero-degree softmax fallback) ----------
    __syncthreads();                          // done with hs: reuse as scratch
    float* cs = hs;                           // 256*4 floats = 4 KB
    {
        float4 colsum = make_float4(acc[0][0] + acc[1][0] + acc[2][0] + acc[3][0],
                                    acc[0][1] + acc[1][1] + acc[2][1] + acc[3][1],
                                    acc[0][2] + acc[1][2] + acc[2][2] + acc[3][2],
                                    acc[0][3] + acc[1][3] + acc[2][3] + acc[3][3]);
        *(float4*)&cs[t * 4] = colsum;
    }
    __syncthreads();
    if (t < 64) {
        int tcq = t >> 2, ccq = t & 3;
        float s = 0.f;
#pragma unroll
        for (int tr2 = 0; tr2 < 16; tr2++) s += cs[(tr2 * 16 + tcq) * 4 + ccq];
        g_meanpart[blockIdx.x * OUT_F + t] = s;
    }
}

// ---------------- 2. warp-per-row: match_any dedup + smem-staged gather -----
// Shuffle count per row ~6 (final reduction only). Dedup within a chunk is one
// __match_any_sync; across chunks it's broadcast LDS against the smem-staged
// earlier ids. Gather weights/ids are read back via broadcast LDS, not SHFL.
__global__ void row_kernel(float* __restrict__ out) {
    __shared__ int   sc[8][CAP];              // per-warp staged dst ids   (4 KB)
    __shared__ float sv[8][CAP];              // per-warp staged weights   (4 KB)
    int wrp = threadIdx.x >> 5;
    int gtid = blockIdx.x * blockDim.x + threadIdx.x;
    int row = gtid >> 5;                      // uniform across the warp
    int lane = gtid & 31;
    if (row >= NN) return;

    int deg = g_deg[row];
    if (deg > CAP) deg = CAP;
    __syncwarp();
    if (lane == 0) g_deg[row] = 0;            // restore zero-invariant for replay

    const int* bucket = &g_cols[row * CAP];
    int*   scw = sc[wrp];
    float* svw = sv[wrp];
    float a0 = 0.f, a1 = 0.f, swl = 0.f;
    float s1r = g_s1[row];

    int nch = (deg + 31) >> 5;
    for (int ch = 0; ch < nch; ch++) {
        int p0 = ch << 5;
        int p = p0 + lane;
        bool valid = p < deg;
        int c = valid ? bucket[p] : -(lane + 1);   // unique sentinel: no false match

        // cross-chunk dedup: broadcast LDS against earlier staged ids
        bool dup = false;
#pragma unroll 8
        for (int q = 0; q < p0; q++)
            if (scw[q] == c) dup = true;
        // within-chunk dedup: one instruction, keep lowest lane of each group
        unsigned peers = __match_any_sync(0xFFFFFFFFu, c);
        if (peers & ((1u << lane) - 1u)) dup = true;

        float w = 0.f;
        if (valid && !dup) {
            float x = s1r + g_s2[c];
            float lr = x > 0.f ? x : ALPHA * x;    // leaky relu
            w = expf(lr);
            swl += w;
        }
        scw[p] = c;
        svw[p] = w;                                // 0 => dup/invalid, skip in gather
        __syncwarp();

        int cnt = deg - p0; if (cnt > 32) cnt = 32;
        for (int j = 0; j < cnt; j++) {
            float wj = svw[p0 + j];                // broadcast LDS (uniform)
            if (wj > 0.f) {
                int cj = scw[p0 + j];
                a0 += wj * g_Wh[cj * OUT_F + lane];
                a1 += wj * g_Wh[cj * OUT_F + 32 + lane];
            }
        }
        __syncwarp();
    }

    float sw = swl;
#pragma unroll
    for (int off = 16; off > 0; off >>= 1)
        sw += __shfl_xor_sync(0xFFFFFFFFu, sw, off);

    if (deg == 0) {
        // softmax over an all -inf row is uniform -> h' = column mean of Wh
        float m0 = 0.f, m1 = 0.f;
        for (int b = 0; b < GEMM_BLOCKS; b++) {
            m0 += g_meanpart[b * OUT_F + lane];
            m1 += g_meanpart[b * OUT_F + 32 + lane];
        }
        a0 = m0 / (float)NN;
        a1 = m1 / (float)NN;
        sw = 1.f;
    }
    float inv = 1.f / sw;
    out[row * OUT_F + lane]      = elu_f(a0 * inv);
    out[row * OUT_F + 32 + lane] = elu_f(a1 * inv);
}

// ---------------- launch ----------------------------------------------------
extern "C" void kernel_launch(void* const* d_in, const int* in_sizes, int n_in,
                              void* d_out, int out_size) {
    const float* h  = (const float*)d_in[0];
    const void*  ei = d_in[1];
    const float* W  = (const float*)d_in[2];
    const float* a  = (const float*)d_in[3];
    float* out = (float*)d_out;

    // opt into >48KB dynamic smem (idempotent, graph-capture-safe)
    cudaFuncSetAttribute(fused_kernel, cudaFuncAttributeMaxDynamicSharedMemorySize,
                         FUSED_SMEM);

    fused_kernel<<<GEMM_BLOCKS + SCAT_BLOCKS, 256, FUSED_SMEM>>>(h, W, a, ei);
    row_kernel<<<(NN * 32 + 255) / 256, 256>>>(out);
}

// round 9
// speedup vs baseline: 2.0837x; 1.2479x over previous
#include <cuda_runtime.h>
#include <cuda_bf16.h>

#define NN 10000
#define IN_F 128
#define OUT_F 64
#define EDGES 320000
#define ALPHA 0.2f
#define GEMM_BM 64
#define GEMM_BLOCKS ((NN + GEMM_BM - 1) / GEMM_BM)   // 157
#define SCAT_BLOCKS 287                               // 157+287 = 444 = 148*3 (one wave)
#define HS_LD 132                                     // row stride (pad, 16B-aligned)
#define FUSED_SMEM ((IN_F * OUT_F + GEMM_BM * HS_LD) * (int)sizeof(float))  // 66560 B
#define CAP 128        // bucket capacity; max degree of Poisson(32) over 10k rows ~ 56

// ---------------- scratch (device globals; zero-initialized at load) --------
__device__ int   g_deg[NN];                  // invariant: zero at kernel_launch entry
__device__ int   g_cols[NN * CAP];           // 5.12 MB padded buckets
__device__ float g_Wh[NN * OUT_F];           // 2.56 MB (L2-resident)
__device__ float g_s1[NN];
__device__ float g_s2[NN];
__device__ float g_meanpart[GEMM_BLOCKS * OUT_F];

// ---------------- helpers ---------------------------------------------------
__device__ __forceinline__ int edge_src(const void* p, int e, int is64) {
    return is64 ? (int)((const long long*)p)[e] : ((const int*)p)[e];
}
__device__ __forceinline__ int edge_dst(const void* p, int e, int is64) {
    return is64 ? (int)((const long long*)p)[EDGES + e] : ((const int*)p)[EDGES + e];
}
__device__ __forceinline__ float elu_f(float x) {
    return x > 0.f ? x : expm1f(x);
}

// ---------------- 1. fused: GEMM(+s1/s2+mean) blocks || scatter blocks ------
// blockIdx < GEMM_BLOCKS : one 64-row tile of Wh = h @ W, fused epilogues.
// blockIdx >= GEMM_BLOCKS: grid-stride bucket scatter of the edge list.
// Both are independent; one launch, one wave (444 blocks, 3/SM @ 65KB smem).
__global__ void fused_kernel(const float* __restrict__ h, const float* __restrict__ W,
                             const float* __restrict__ a, const void* __restrict__ ei) {
    int t = threadIdx.x;

    if (blockIdx.x >= GEMM_BLOCKS) {
        // ------------------- scatter role --------------------------------
        // dtype detect: warp 0 reads the FIRST 32 int64s (L2 broadcast).
        // int64 data: all are src ids in [0, NN). int32 data: each read packs
        // two node ids -> looks valid only if high word == 0 (P = 1e-4 each);
        // P(all 32 look valid) = 1e-128 -> detection certain.
        __shared__ int s_is64;
        if (t < 32) {
            const long long* p = (const long long*)ei;
            long long v = p[t];
            bool bad = (v < 0 || v >= NN);
            unsigned m = __ballot_sync(0xFFFFFFFFu, bad);
            if (t == 0) s_is64 = (m == 0u) ? 1 : 0;
        }
        __syncthreads();
        int is64 = s_is64;
        int sbid = blockIdx.x - GEMM_BLOCKS;
        for (int e = sbid * 256 + t; e < EDGES; e += SCAT_BLOCKS * 256) {
            int s = edge_src(ei, e, is64);
            int d = edge_dst(ei, e, is64);
            int pos = atomicAdd(&g_deg[s], 1);
            if (pos < CAP) g_cols[s * CAP + pos] = d;  // clamp (never hit in practice)
        }
        return;
    }

    // ---------------------- gemm role ------------------------------------
    extern __shared__ float smem[];
    float* Ws = smem;                        // [128][64]  32 KB, [k][c]
    float* hs = smem + IN_F * OUT_F;         // [64][132]  33.8 KB, [r][k] row-major
    int row0 = blockIdx.x * GEMM_BM;

    for (int i = t; i < IN_F * OUT_F; i += 256) Ws[i] = W[i];
    // coalesced float4 global loads, conflict-free float4 smem stores
    for (int i = t; i < GEMM_BM * (IN_F / 4); i += 256) {
        int r = i >> 5, cq = i & 31;         // r in [0,64), cq in [0,32)
        int gr = row0 + r;
        float4 v = make_float4(0.f, 0.f, 0.f, 0.f);
        if (gr < NN) v = *(const float4*)&h[gr * IN_F + cq * 4];
        *(float4*)&hs[r * HS_LD + cq * 4] = v;
    }
    __syncthreads();

    int tr = t >> 4, tc = t & 15;
    int rbase = tr * 4, cbase = tc * 4;
    const float* h0 = &hs[(rbase + 0) * HS_LD];
    const float* h1 = &hs[(rbase + 1) * HS_LD];
    const float* h2 = &hs[(rbase + 2) * HS_LD];
    const float* h3 = &hs[(rbase + 3) * HS_LD];
    float acc[4][4] = {};
#pragma unroll 4
    for (int k = 0; k < IN_F; k++) {
        float4 wv = *(const float4*)&Ws[k * OUT_F + cbase];
        float a0v = h0[k], a1v = h1[k], a2v = h2[k], a3v = h3[k];  // broadcast LDS
        acc[0][0] += a0v * wv.x; acc[0][1] += a0v * wv.y; acc[0][2] += a0v * wv.z; acc[0][3] += a0v * wv.w;
        acc[1][0] += a1v * wv.x; acc[1][1] += a1v * wv.y; acc[1][2] += a1v * wv.z; acc[1][3] += a1v * wv.w;
        acc[2][0] += a2v * wv.x; acc[2][1] += a2v * wv.y; acc[2][2] += a2v * wv.z; acc[2][3] += a2v * wv.w;
        acc[3][0] += a3v * wv.x; acc[3][1] += a3v * wv.y; acc[3][2] += a3v * wv.z; acc[3][3] += a3v * wv.w;
    }

    // store Wh (float4 per row)
#pragma unroll
    for (int j = 0; j < 4; j++) {
        int gr = row0 + rbase + j;
        if (gr < NN) {
            float4 v = make_float4(acc[j][0], acc[j][1], acc[j][2], acc[j][3]);
            *(float4*)&g_Wh[gr * OUT_F + cbase] = v;
        }
    }

    // ---- fused s1/s2: s1[r] = Wh[r,:]·a[0:64], s2[r] = Wh[r,:]·a[64:128] ----
    float av1[4], av2[4];
#pragma unroll
    for (int c = 0; c < 4; c++) { av1[c] = a[cbase + c]; av2[c] = a[64 + cbase + c]; }
#pragma unroll
    for (int j = 0; j < 4; j++) {
        float p1 = acc[j][0]*av1[0] + acc[j][1]*av1[1] + acc[j][2]*av1[2] + acc[j][3]*av1[3];
        float p2 = acc[j][0]*av2[0] + acc[j][1]*av2[1] + acc[j][2]*av2[2] + acc[j][3]*av2[3];
        // xor-reduce over the 16 col-group lanes (xor of bits 0..3 stays in row group)
#pragma unroll
        for (int off = 8; off > 0; off >>= 1) {
            p1 += __shfl_xor_sync(0xFFFFFFFFu, p1, off);
            p2 += __shfl_xor_sync(0xFFFFFFFFu, p2, off);
        }
        int gr = row0 + rbase + j;
        if (tc == 0 && gr < NN) { g_s1[gr] = p1; g_s2[gr] = p2; }
    }

    // ---- fused column-sum partials (zero-degree softmax fallback) ----------
    __syncthreads();                          // done with hs: reuse as scratch
    float* cs = hs;                           // 256*4 floats = 4 KB
    {
        float4 colsum = make_float4(acc[0][0] + acc[1][0] + acc[2][0] + acc[3][0],
                                    acc[0][1] + acc[1][1] + acc[2][1] + acc[3][1],
                                    acc[0][2] + acc[1][2] + acc[2][2] + acc[3][2],
                                    acc[0][3] + acc[1][3] + acc[2][3] + acc[3][3]);
        *(float4*)&cs[t * 4] = colsum;
    }
    __syncthreads();
    if (t < 64) {
        int tcq = t >> 2, ccq = t & 3;
        float s = 0.f;
#pragma unroll
        for (int tr2 = 0; tr2 < 16; tr2++) s += cs[(tr2 * 16 + tcq) * 4 + ccq];
        g_meanpart[blockIdx.x * OUT_F + t] = s;
    }
}

// ---------------- 2. warp-per-row: stage+dedup, then branch-free gather -----
// Phase A: stage all chunks into per-warp smem with match_any within-chunk
// dedup and broadcast-LDS cross-chunk dedup. Dup/invalid entries get w=0 and
// keep a SAFE (or sentinel) id. Phase B: one flat, unrolled, branch-free
// gather: per neighbor 1 LDG.64 (float2) + 2 FFMA; unroll-4 gives MLP>=4.
__global__ void row_kernel(float* __restrict__ out) {
    __shared__ int   sc[8][CAP];              // per-warp staged dst ids   (4 KB)
    __shared__ float sv[8][CAP];              // per-warp staged weights   (4 KB)
    int wrp = threadIdx.x >> 5;
    int gtid = blockIdx.x * blockDim.x + threadIdx.x;
    int row = gtid >> 5;                      // uniform across the warp
    int lane = gtid & 31;
    if (row >= NN) return;

    int deg = g_deg[row];
    if (deg > CAP) deg = CAP;
    __syncwarp();
    if (lane == 0) g_deg[row] = 0;            // restore zero-invariant for replay

    const int* bucket = &g_cols[row * CAP];
    int*   scw = sc[wrp];
    float* svw = sv[wrp];
    float s1r = g_s1[row];
    float swl = 0.f;

    // -------- Phase A: stage + dedup ----------------------------------------
    int nch = (deg + 31) >> 5;
    for (int ch = 0; ch < nch; ch++) {
        int p0 = ch << 5;
        int p = p0 + lane;
        bool valid = p < deg;
        int c = valid ? bucket[p] : -(lane + 1);   // unique sentinel: no false match

        bool dup = false;
        for (int q = 0; q < p0; q++)               // cross-chunk: broadcast LDS
            if (scw[q] == c) dup = true;
        unsigned peers = __match_any_sync(0xFFFFFFFFu, c);
        if (peers & ((1u << lane) - 1u)) dup = true;  // keep lowest lane

        float w = 0.f;
        if (valid && !dup) {
            float x = s1r + g_s2[c];
            float lr = x > 0.f ? x : ALPHA * x;    // leaky relu
            w = expf(lr);
            swl += w;
        }
        scw[p] = c;                                // real id kept for dedup compares
        svw[p] = w;                                // 0 => dup/invalid
        __syncwarp();
    }

    // -------- Phase B: branch-free unrolled gather ---------------------------
    float a0 = 0.f, a1 = 0.f;
    int tot = nch << 5;                            // staged slots (all populated)
#pragma unroll 4
    for (int j = 0; j < tot; j++) {
        float wj = svw[j];                         // broadcast LDS
        int cj = scw[j];
        cj = cj < 0 ? 0 : cj;                      // sanitize sentinel (wj==0 there)
        float2 v = *(const float2*)&g_Wh[cj * OUT_F + 2 * lane];
        a0 += wj * v.x;
        a1 += wj * v.y;
    }

    float sw = swl;
#pragma unroll
    for (int off = 16; off > 0; off >>= 1)
        sw += __shfl_xor_sync(0xFFFFFFFFu, sw, off);

    if (deg == 0) {
        // softmax over an all -inf row is uniform -> h' = column mean of Wh
        float m0 = 0.f, m1 = 0.f;
        for (int b = 0; b < GEMM_BLOCKS; b++) {
            m0 += g_meanpart[b * OUT_F + 2 * lane];
            m1 += g_meanpart[b * OUT_F + 2 * lane + 1];
        }
        a0 = m0 / (float)NN;
        a1 = m1 / (float)NN;
        sw = 1.f;
    }
    float inv = 1.f / sw;
    float2 r = make_float2(elu_f(a0 * inv), elu_f(a1 * inv));
    *(float2*)&out[row * OUT_F + 2 * lane] = r;
}

// ---------------- launch ----------------------------------------------------
extern "C" void kernel_launch(void* const* d_in, const int* in_sizes, int n_in,
                              void* d_out, int out_size) {
    const float* h  = (const float*)d_in[0];
    const void*  ei = d_in[1];
    const float* W  = (const float*)d_in[2];
    const float* a  = (const float*)d_in[3];
    float* out = (float*)d_out;

    // opt into >48KB dynamic smem (idempotent, graph-capture-safe)
    cudaFuncSetAttribute(fused_kernel, cudaFuncAttributeMaxDynamicSharedMemorySize,
                         FUSED_SMEM);

    fused_kernel<<<GEMM_BLOCKS + SCAT_BLOCKS, 256, FUSED_SMEM>>>(h, W, a, ei);
    row_kernel<<<(NN * 32 + 255) / 256, 256>>>(out);
}